// round 13
// baseline (speedup 1.0000x reference)
#include <cuda_runtime.h>
#include <cuda_fp16.h>
#include <math.h>
#include <stdint.h>

#define DIM 768
#define HID 1536
#define BATCH 64
#define TOK 256
#define MROWS (BATCH*TOK)   /* 16384 */
#define LN_EPS 1e-6f

/* ------------------------------ scratch ------------------------------ */
__device__ float   g_t [MROWS*DIM];        /* residual stream fp32   48 MB */
__device__ __half  g_yh[MROWS*DIM];        /* FFT out fp16           24 MB */
__device__ float2  g_stat[MROWS];          /* ln1 (sum, sumsq) per row     */
__device__ __half2 g_sp[BATCH*16*9*DIM];   /* spectrum (re,im) fp16  28 MB */
__device__ __half  g_xh[MROWS*DIM];        /* im2col fp16            24 MB */
__device__ __half  g_ah[MROWS*DIM];        /* ln2 out fp16           24 MB */
__device__ __half  g_hh[MROWS*HID];        /* gelu hidden fp16       48 MB */
__device__ __half  g_w1h[8*HID*DIM];       /* fc1_w fp16             19 MB */
__device__ __half  g_w2h[8*DIM*HID];       /* fc2_w fp16             19 MB */
__device__ __half  g_wch[DIM*DIM];         /* conv_w fp16           1.2 MB */

/* ------------------------------ helpers ------------------------------ */
__global__ __launch_bounds__(256) void round_h(const float* __restrict__ s,
                                               __half* __restrict__ d, int n) {
    int i = blockIdx.x * 256 + threadIdx.x;
    if (i < n) d[i] = __float2half(s[i]);
}

/* vectorized im2col: one thread = one 16-px patch row (64B in, 32B out) */
__global__ __launch_bounds__(256) void im2col_k(const float* __restrict__ x,
                                                __half* __restrict__ out) {
    int gid = blockIdx.x * 256 + threadIdx.x;      /* 16384*48 */
    int r48 = gid % 48;
    int m   = gid / 48;
    int c   = r48 >> 4, ph = r48 & 15;
    int b = m >> 8;      int p  = m & 255;
    int hp = p >> 4;     int wp = p & 15;
    const float4* src = (const float4*)(x + ((size_t)(b*3 + c)*256 + hp*16 + ph)*256 + wp*16);
    __half2* dst = (__half2*)(out + (size_t)m * DIM + c*256 + ph*16);
    #pragma unroll
    for (int q = 0; q < 4; q++) {
        float4 v = src[q];
        dst[q*2+0] = __floats2half2_rn(v.x, v.y);
        dst[q*2+1] = __floats2half2_rn(v.z, v.w);
    }
}

__device__ __forceinline__ void ldsm4(uint32_t& r0, uint32_t& r1,
                                      uint32_t& r2, uint32_t& r3, uint32_t addr) {
    asm volatile("ldmatrix.sync.aligned.m8n8.x4.shared.b16 {%0,%1,%2,%3}, [%4];"
                 : "=r"(r0), "=r"(r1), "=r"(r2), "=r"(r3) : "r"(addr));
}
__device__ __forceinline__ void mma_f16(float* c, uint32_t a0, uint32_t a1,
                                        uint32_t a2, uint32_t a3,
                                        uint32_t b0, uint32_t b1) {
    asm volatile(
        "mma.sync.aligned.m16n8k16.row.col.f32.f16.f16.f32 "
        "{%0,%1,%2,%3},{%4,%5,%6,%7},{%8,%9},{%0,%1,%2,%3};"
        : "+f"(c[0]), "+f"(c[1]), "+f"(c[2]), "+f"(c[3])
        : "r"(a0), "r"(a1), "r"(a2), "r"(a3), "r"(b0), "r"(b1));
}

/* ------------------------------ fp16 tensor-core GEMM ------------------------------ */
/* C[M,N] = A[M,K] * B[N,K]^T, fp16 in, fp32 acc.
   CTA 128x64, K chunks of 64 (BK=64), 8 warps (4 M x 2 N), warp tile 32x32.
   3-stage cp.async pipeline (dynamic smem, 83KB), ONE sync per 64-K chunk.
   smem row stride 72 halves (144B): row-start banks {0,4,..,28}, conflict-free.
   EPI: 0 = fp32 +bias+pos (+stats)   1 = fp16 gelu(.+bias)   2 = fp32 C += . + bias (+stats) */

#define RSTR 72
#define STGA (128*RSTR)
#define STGB (64*RSTR)
#define STG  (STGA+STGB)        /* halves per stage (13824) */
#define GSMEM (3*STG*2)         /* 82944 bytes */

template<int EPI>
__global__ __launch_bounds__(256) void gemm_mma(
    const __half* __restrict__ A, const __half* __restrict__ B,
    const float* __restrict__ bias, const float* __restrict__ extra,
    void* __restrict__ Cv, float2* __restrict__ stat, int M, int N, int K)
{
    extern __shared__ __half sm[];

    const int tid  = threadIdx.x;
    const int wid  = tid >> 5, lane = tid & 31;
    const int g    = lane >> 2, t = lane & 3;
    const int wm   = (wid & 3) * 32;
    const int wn   = (wid >> 2) * 32;
    const int m0   = blockIdx.y * 128, n0 = blockIdx.x * 64;

    float acc[2][4][4];
    #pragma unroll
    for (int i = 0; i < 2; i++)
        #pragma unroll
        for (int j = 0; j < 4; j++)
            #pragma unroll
            for (int q = 0; q < 4; q++) acc[i][j][q] = 0.f;

    const int nk = K >> 6;
    const int lrow = tid >> 3, lc = tid & 7;   /* 32 rows per pass, 8 chunks of 16B */

    auto load_tiles = [&](int k0, int s) {
        __half* as = sm + s * STG;
        __half* bs = as + STGA;
        #pragma unroll
        for (int l = 0; l < 4; l++) {
            int row = lrow + l * 32;
            const __half* gA = A + (size_t)(m0 + row) * K + k0 + lc * 8;
            uint32_t sa = (uint32_t)__cvta_generic_to_shared(as + row * RSTR + lc * 8);
            asm volatile("cp.async.cg.shared.global [%0], [%1], 16;" :: "r"(sa), "l"(gA));
        }
        #pragma unroll
        for (int l = 0; l < 2; l++) {
            int row = lrow + l * 32;
            const __half* gB = B + (size_t)(n0 + row) * K + k0 + lc * 8;
            uint32_t sb = (uint32_t)__cvta_generic_to_shared(bs + row * RSTR + lc * 8);
            asm volatile("cp.async.cg.shared.global [%0], [%1], 16;" :: "r"(sb), "l"(gB));
        }
        asm volatile("cp.async.commit_group;");
    };

    const int lq = lane >> 3, lr = lane & 7;
    const int a_row = (lq & 1) * 8 + lr;
    const int a_chk = lq >> 1;
    const int b_row = (lq >> 1) * 8 + lr;
    const int b_chk = lq & 1;

    load_tiles(0, 0);
    if (nk > 1) load_tiles(64, 1);

    int cur = 0, pre = 2;
    for (int it = 0; it < nk; it++) {
        if (it == nk - 1) { asm volatile("cp.async.wait_group 0;"); }
        else              { asm volatile("cp.async.wait_group 1;"); }
        __syncthreads();
        if (it + 2 < nk) load_tiles((it + 2) << 6, pre);

        const __half* as = sm + cur * STG;
        const __half* bs = as + STGA;
        #pragma unroll
        for (int ks = 0; ks < 4; ks++) {
            uint32_t aF[2][4];
            #pragma unroll
            for (int mi = 0; mi < 2; mi++) {
                uint32_t ad = (uint32_t)__cvta_generic_to_shared(
                    as + (wm + mi * 16 + a_row) * RSTR + (ks * 2 + a_chk) * 8);
                ldsm4(aF[mi][0], aF[mi][1], aF[mi][2], aF[mi][3], ad);
            }
            #pragma unroll
            for (int ni2 = 0; ni2 < 2; ni2++) {
                uint32_t b0, b1, b2, b3;
                uint32_t bd = (uint32_t)__cvta_generic_to_shared(
                    bs + (wn + ni2 * 16 + b_row) * RSTR + (ks * 2 + b_chk) * 8);
                ldsm4(b0, b1, b2, b3, bd);
                #pragma unroll
                for (int mi = 0; mi < 2; mi++) {
                    mma_f16(acc[mi][ni2*2],   aF[mi][0], aF[mi][1], aF[mi][2], aF[mi][3], b0, b1);
                    mma_f16(acc[mi][ni2*2+1], aF[mi][0], aF[mi][1], aF[mi][2], aF[mi][3], b2, b3);
                }
            }
        }
        cur = (cur == 2) ? 0 : cur + 1;
        pre = (pre == 2) ? 0 : pre + 1;
    }

    /* epilogue (+ per-row stats of produced residual for EPI 0/2) */
    float rs[2][2] = {{0.f,0.f},{0.f,0.f}};
    float rq[2][2] = {{0.f,0.f},{0.f,0.f}};

    #pragma unroll
    for (int mi = 0; mi < 2; mi++) {
        #pragma unroll
        for (int ni = 0; ni < 4; ni++) {
            int row = m0 + wm + mi * 16 + g;
            int col = n0 + wn + ni * 8 + 2 * t;
            float bc0 = bias[col], bc1 = bias[col + 1];
            #pragma unroll
            for (int hf = 0; hf < 2; hf++) {
                int m = row + hf * 8;
                float v0 = acc[mi][ni][hf*2]   + bc0;
                float v1 = acc[mi][ni][hf*2+1] + bc1;
                size_t o = (size_t)m * N + col;
                if (EPI == 0) {
                    const float* e = extra + (size_t)(m & 255) * N + col;
                    v0 += e[0]; v1 += e[1];
                    *(float2*)((float*)Cv + o) = make_float2(v0, v1);
                    rs[mi][hf] += v0 + v1;
                    rq[mi][hf] += v0*v0 + v1*v1;
                } else if (EPI == 1) {
                    v0 = 0.5f * v0 * (1.0f + erff(v0 * 0.70710678118654752f));
                    v1 = 0.5f * v1 * (1.0f + erff(v1 * 0.70710678118654752f));
                    *(__half2*)((__half*)Cv + o) = __floats2half2_rn(v0, v1);
                } else {
                    float2 old = *(float2*)((float*)Cv + o);
                    float n0f = old.x + v0, n1f = old.y + v1;
                    *(float2*)((float*)Cv + o) = make_float2(n0f, n1f);
                    rs[mi][hf] += n0f + n1f;
                    rq[mi][hf] += n0f*n0f + n1f*n1f;
                }
            }
        }
    }

    if (EPI != 1) {
        #pragma unroll
        for (int mi = 0; mi < 2; mi++) {
            #pragma unroll
            for (int hf = 0; hf < 2; hf++) {
                float s = rs[mi][hf], q = rq[mi][hf];
                s += __shfl_xor_sync(0xffffffffu, s, 1);
                q += __shfl_xor_sync(0xffffffffu, q, 1);
                s += __shfl_xor_sync(0xffffffffu, s, 2);
                q += __shfl_xor_sync(0xffffffffu, q, 2);
                if (t == 0) {
                    int m = m0 + wm + mi * 16 + g + hf * 8;
                    atomicAdd(&stat[m].x, s);
                    atomicAdd(&stat[m].y, q);
                }
            }
        }
    }
}

/* ------------------------------ reductions ------------------------------ */
__device__ __forceinline__ float2 block_reduce2(float s, float ss, float2* red) {
    int lane = threadIdx.x & 31, w = threadIdx.x >> 5;
    #pragma unroll
    for (int o = 16; o; o >>= 1) {
        s  += __shfl_down_sync(0xffffffffu, s,  o);
        ss += __shfl_down_sync(0xffffffffu, ss, o);
    }
    __syncthreads();
    if (lane == 0) red[w] = make_float2(s, ss);
    __syncthreads();
    if (w == 0) {
        float2 v = (lane < 8) ? red[lane] : make_float2(0.f, 0.f);
        float a = v.x, bq = v.y;
        #pragma unroll
        for (int o = 4; o; o >>= 1) {
            a  += __shfl_down_sync(0xffffffffu, a,  o);
            bq += __shfl_down_sync(0xffffffffu, bq, o);
        }
        if (lane == 0) red[0] = make_float2(a, bq);
    }
    __syncthreads();
    return red[0];
}

/* LayerNorm over fp16 input -> fp16 out (feeds fc1) */
__global__ __launch_bounds__(256) void ln_to_h(const __half* __restrict__ in,
                                               __half* __restrict__ out,
                                               const float* __restrict__ w,
                                               const float* __restrict__ b) {
    __shared__ float2 red[8];
    int row = blockIdx.x, t = threadIdx.x;
    const __half* r = in + (size_t)row * DIM;
    float v0 = __half2float(r[t]);
    float v1 = __half2float(r[t+256]);
    float v2 = __half2float(r[t+512]);
    float2 R = block_reduce2(v0+v1+v2, v0*v0+v1*v1+v2*v2, red);
    float mean = R.x * (1.f/768.f);
    float var  = R.y * (1.f/768.f) - mean*mean;
    float rs = rsqrtf(var + LN_EPS);
    __half* o = out + (size_t)row * DIM;
    o[t]     = __float2half((v0-mean)*rs*w[t]     + b[t]);
    o[t+256] = __float2half((v1-mean)*rs*w[t+256] + b[t+256]);
    o[t+512] = __float2half((v2-mean)*rs*w[t+512] + b[t+512]);
}

/* ------------------------------ 16-pt radix-4 complex FFT ------------------------------ */
/* In-place, natural order in and out.  sgn = -1 forward, +1 inverse. */
__device__ __forceinline__ void fft16_r4(float* xr, float* xi,
                                         const float* ct, const float* st,
                                         const float sgn) {
    float yr[4][4], yi[4][4];
    #pragma unroll
    for (int b = 0; b < 4; b++) {
        float a0r=xr[b],    a0i=xi[b];
        float a1r=xr[4+b],  a1i=xi[4+b];
        float a2r=xr[8+b],  a2i=xi[8+b];
        float a3r=xr[12+b], a3i=xi[12+b];
        float t0r=a0r+a2r, t0i=a0i+a2i;
        float t1r=a0r-a2r, t1i=a0i-a2i;
        float t2r=a1r+a3r, t2i=a1i+a3i;
        float t3r=a1r-a3r, t3i=a1i-a3i;
        float w3r = -sgn*t3i, w3i = sgn*t3r;
        float Br[4], Bi[4];
        Br[0]=t0r+t2r; Bi[0]=t0i+t2i;
        Br[1]=t1r+w3r; Bi[1]=t1i+w3i;
        Br[2]=t0r-t2r; Bi[2]=t0i-t2i;
        Br[3]=t1r-w3r; Bi[3]=t1i-w3i;
        #pragma unroll
        for (int c = 0; c < 4; c++) {
            int m = b * c;
            float wr = ct[m], wi = sgn*st[m];
            yr[c][b] = Br[c]*wr - Bi[c]*wi;
            yi[c][b] = Br[c]*wi + Bi[c]*wr;
        }
    }
    #pragma unroll
    for (int c = 0; c < 4; c++) {
        float t0r=yr[c][0]+yr[c][2], t0i=yi[c][0]+yi[c][2];
        float t1r=yr[c][0]-yr[c][2], t1i=yi[c][0]-yi[c][2];
        float t2r=yr[c][1]+yr[c][3], t2i=yi[c][1]+yi[c][3];
        float t3r=yr[c][1]-yr[c][3], t3i=yi[c][1]-yi[c][3];
        float w3r=-sgn*t3i, w3i=sgn*t3r;
        xr[c]    = t0r+t2r;  xi[c]    = t0i+t2i;
        xr[c+4]  = t1r+w3r;  xi[c+4]  = t1i+w3i;
        xr[c+8]  = t0r-t2r;  xi[c+8]  = t0i-t2i;
        xr[c+12] = t1r-w3r;  xi[c+12] = t1i-w3i;
    }
}

/* ------------------------------ FFT stages ------------------------------ */
/* F1: ln1 (from fused atomic stats) + radix-4 real FFT along w (16 -> 9) */
__global__ __launch_bounds__(256) void fft_fwd_w(const float* __restrict__ tt,
                                                 const float2* __restrict__ stat,
                                                 const float* __restrict__ lw,
                                                 const float* __restrict__ lb,
                                                 __half2* __restrict__ sp) {
    __shared__ float ct[16], stab[16], shm[16], shr[16];
    int t = threadIdx.x;
    int gid = blockIdx.x * 256 + t;
    int d = gid % DIM; int hb = gid / DIM; int h = hb & 15; int b = hb >> 4;
    int rowbase = b*256 + h*16;
    if (t < 16) {
        ct[t] = cospif(t * 0.125f); stab[t] = sinpif(t * 0.125f);
        float2 sq = __ldg(&stat[rowbase + t]);
        float mean = sq.x * (1.f/768.f);
        float var  = sq.y * (1.f/768.f) - mean*mean;
        shm[t] = mean;
        shr[t] = rsqrtf(var + LN_EPS);
    }
    __syncthreads();

    float wd = lw[d], bd = lb[d];
    float v[16], vi[16];
    const float* src = tt + (size_t)rowbase * DIM + d;
    #pragma unroll
    for (int w = 0; w < 16; w++) {
        v[w]  = (src[(size_t)w * DIM] - shm[w]) * shr[w] * wd + bd;
        vi[w] = 0.f;
    }
    fft16_r4(v, vi, ct, stab, -1.f);

    size_t o = (size_t)(b*16 + h) * 9 * DIM + d;
    #pragma unroll
    for (int k = 0; k < 9; k++)
        sp[o + (size_t)k * DIM] = __floats2half2_rn(v[k], vi[k]);
}

/* F2: radix-4 FFT(h) * filter * radix-4 iFFT(h) */
__global__ __launch_bounds__(256) void fft_h_mod(__half2* __restrict__ sp,
                                                 const float* __restrict__ cw) {
    __shared__ float ct[16], st[16];
    int t = threadIdx.x;
    if (t < 16) { ct[t] = cospif(t * 0.125f); st[t] = sinpif(t * 0.125f); }
    __syncthreads();
    int gid = blockIdx.x * 256 + t;
    int d = gid % DIM; int kb = gid / DIM; int k = kb % 9; int b = kb / 9;
    size_t base = ((size_t)b * 16 * 9 + k) * DIM + d;
    float gr[16], gi[16];
    #pragma unroll
    for (int h = 0; h < 16; h++) {
        float2 f = __half22float2(sp[base + (size_t)h * 9 * DIM]);
        gr[h] = f.x; gi[h] = f.y;
    }
    fft16_r4(gr, gi, ct, st, -1.f);
    #pragma unroll
    for (int u = 0; u < 16; u++) {
        const float* wp = cw + ((size_t)(u*9 + k) * DIM + d) * 2;
        float wr = wp[0], wi = wp[1];
        float ar = gr[u], ai = gi[u];
        gr[u] = ar * wr - ai * wi;
        gi[u] = ar * wi + ai * wr;
    }
    fft16_r4(gr, gi, ct, st, 1.f);
    #pragma unroll
    for (int h = 0; h < 16; h++)
        sp[base + (size_t)h * 9 * DIM] = __floats2half2_rn(gr[h], gi[h]);
}

/* radix-4 hermitian inverse FFT along w (9 -> 16) -> fp16 y */
__global__ __launch_bounds__(256) void fft_inv_w(const __half2* __restrict__ sp,
                                                 __half* __restrict__ y) {
    __shared__ float ct[16], st[16];
    int t = threadIdx.x;
    if (t < 16) { ct[t] = cospif(t * 0.125f); st[t] = sinpif(t * 0.125f); }
    __syncthreads();
    int gid = blockIdx.x * 256 + t;
    int d = gid % DIM; int hb = gid / DIM; int h = hb & 15; int b = hb >> 4;
    size_t base = (size_t)(b*16 + h) * 9 * DIM + d;
    float xr[16], xi[16];
    {
        float2 f0 = __half22float2(sp[base]);
        xr[0] = f0.x; xi[0] = 0.f;
        #pragma unroll
        for (int k = 1; k < 8; k++) {
            float2 f = __half22float2(sp[base + (size_t)k * DIM]);
            xr[k] = f.x;      xi[k] = f.y;
            xr[16-k] = f.x;   xi[16-k] = -f.y;
        }
        float2 f8 = __half22float2(sp[base + (size_t)8 * DIM]);
        xr[8] = f8.x; xi[8] = 0.f;
    }
    fft16_r4(xr, xi, ct, st, 1.f);
    __half* dst = y + (size_t)(b*256 + h*16) * DIM + d;
    #pragma unroll
    for (int w = 0; w < 16; w++)
        dst[(size_t)w * DIM] = __float2half(xr[w] * (1.f / 256.f));
}

/* ------------------------------ final LN + mean + head ------------------------------ */
__global__ __launch_bounds__(256) void head_k(const float* __restrict__ tt,
                                              const float* __restrict__ nw,
                                              const float* __restrict__ nb,
                                              const float* __restrict__ hw,
                                              const float* __restrict__ hb,
                                              float* __restrict__ out) {
    __shared__ float2 red[8];
    int b = blockIdx.x, t = threadIdx.x;
    float a0 = 0.f, a1 = 0.f, a2 = 0.f;
    for (int p = 0; p < 256; p++) {
        const float* r = tt + (size_t)(b*256 + p) * DIM;
        float v0 = r[t], v1 = r[t+256], v2 = r[t+512];
        float2 R = block_reduce2(v0+v1+v2, v0*v0+v1*v1+v2*v2, red);
        float mean = R.x * (1.f/768.f);
        float var  = R.y * (1.f/768.f) - mean*mean;
        float rs = rsqrtf(var + LN_EPS);
        a0 += (v0-mean)*rs; a1 += (v1-mean)*rs; a2 += (v2-mean)*rs;
    }
    float f0 = a0 * nw[t]     * (1.f/256.f) + nb[t];
    float f1 = a1 * nw[t+256] * (1.f/256.f) + nb[t+256];
    float f2 = a2 * nw[t+512] * (1.f/256.f) + nb[t+512];
    float p0 = f0*hw[t]       + f1*hw[t+256]     + f2*hw[t+512];
    float p1 = f0*hw[768+t]   + f1*hw[768+t+256] + f2*hw[768+t+512];
    float2 R = block_reduce2(p0, p1, red);
    if (t == 0) {
        out[b*2 + 0] = R.x + hb[0];
        out[b*2 + 1] = R.y + hb[1];
    }
}

/* ------------------------------ launch ------------------------------ */
extern "C" void kernel_launch(void* const* d_in, const int* in_sizes, int n_in,
                              void* d_out, int out_size) {
    const float* x      = (const float*)d_in[0];
    const float* conv_w = (const float*)d_in[1];
    const float* conv_b = (const float*)d_in[2];
    const float* pos    = (const float*)d_in[3];
    const float* cw     = (const float*)d_in[4];
    const float* ln1w   = (const float*)d_in[5];
    const float* ln1b   = (const float*)d_in[6];
    const float* ln2w   = (const float*)d_in[7];
    const float* ln2b   = (const float*)d_in[8];
    const float* fc1w   = (const float*)d_in[9];
    const float* fc1b   = (const float*)d_in[10];
    const float* fc2w   = (const float*)d_in[11];
    const float* fc2b   = (const float*)d_in[12];
    const float* normw  = (const float*)d_in[13];
    const float* normb  = (const float*)d_in[14];
    const float* headw  = (const float*)d_in[15];
    const float* headb  = (const float*)d_in[16];
    float* out = (float*)d_out;
    (void)in_sizes; (void)n_in; (void)out_size;

    float *pt;
    float2* pstat;
    __half2* psp;
    __half *pyh, *pxh, *pah, *phh, *pw1h, *pw2h, *pwch;
    cudaGetSymbolAddress((void**)&pt,    g_t);
    cudaGetSymbolAddress((void**)&pyh,   g_yh);
    cudaGetSymbolAddress((void**)&pstat, g_stat);
    cudaGetSymbolAddress((void**)&psp,   g_sp);
    cudaGetSymbolAddress((void**)&pxh,   g_xh);
    cudaGetSymbolAddress((void**)&pah,   g_ah);
    cudaGetSymbolAddress((void**)&phh,   g_hh);
    cudaGetSymbolAddress((void**)&pw1h,  g_w1h);
    cudaGetSymbolAddress((void**)&pw2h,  g_w2h);
    cudaGetSymbolAddress((void**)&pwch,  g_wch);

    static bool attr_set = false;
    if (!attr_set) {
        cudaFuncSetAttribute(gemm_mma<0>, cudaFuncAttributeMaxDynamicSharedMemorySize, GSMEM);
        cudaFuncSetAttribute(gemm_mma<1>, cudaFuncAttributeMaxDynamicSharedMemorySize, GSMEM);
        cudaFuncSetAttribute(gemm_mma<2>, cudaFuncAttributeMaxDynamicSharedMemorySize, GSMEM);
        attr_set = true;
    }

    /* fp16 weights */
    round_h<<<(DIM*DIM + 255)/256, 256>>>(conv_w, pwch, DIM*DIM);
    round_h<<<(8*HID*DIM + 255)/256, 256>>>(fc1w, pw1h, 8*HID*DIM);
    round_h<<<(8*DIM*HID + 255)/256, 256>>>(fc2w, pw2h, 8*DIM*HID);

    /* patch embed (+ ln1 stats for layer 0) */
    im2col_k<<<(MROWS * 48) / 256, 256>>>(x, pxh);
    cudaMemsetAsync(pstat, 0, MROWS * sizeof(float2));
    gemm_mma<0><<<dim3(DIM/64, MROWS/128), 256, GSMEM>>>(pxh, pwch, conv_b, pos, pt, pstat,
                                                         MROWS, DIM, DIM);

    const int nF1 = (BATCH * 16 * DIM) / 256;
    const int nF2 = (BATCH * 9  * DIM) / 256;

    for (int i = 0; i < 8; i++) {
        fft_fwd_w<<<nF1, 256>>>(pt, pstat, ln1w + i*DIM, ln1b + i*DIM, psp);
        fft_h_mod<<<nF2, 256>>>(psp, cw + (size_t)i * 16 * 9 * DIM * 2);
        fft_inv_w<<<nF1, 256>>>(psp, pyh);
        ln_to_h<<<MROWS, 256>>>(pyh, pah, ln2w + i*DIM, ln2b + i*DIM);
        gemm_mma<1><<<dim3(HID/64, MROWS/128), 256, GSMEM>>>(
            pah, pw1h + (size_t)i*HID*DIM, fc1b + i*HID, nullptr, phh, nullptr,
            MROWS, HID, DIM);
        cudaMemsetAsync(pstat, 0, MROWS * sizeof(float2));
        gemm_mma<2><<<dim3(DIM/64, MROWS/128), 256, GSMEM>>>(
            phh, pw2h + (size_t)i*DIM*HID, fc2b + i*DIM, nullptr, pt, pstat,
            MROWS, DIM, HID);
    }

    head_k<<<BATCH, 256>>>(pt, normw, normb, headw, headb, out);
}

// round 14
// speedup vs baseline: 1.0646x; 1.0646x over previous
#include <cuda_runtime.h>
#include <cuda_fp16.h>
#include <math.h>
#include <stdint.h>

#define DIM 768
#define HID 1536
#define BATCH 64
#define TOK 256
#define MROWS (BATCH*TOK)   /* 16384 */
#define LN_EPS 1e-6f

/* ------------------------------ scratch ------------------------------ */
__device__ float   g_t [MROWS*DIM];        /* residual stream fp32   48 MB */
__device__ __half  g_yh[MROWS*DIM];        /* FFT out fp16           24 MB */
__device__ float2  g_stat[MROWS];          /* ln1 (sum, sumsq) per row     */
__device__ __half  g_xh[MROWS*DIM];        /* im2col fp16            24 MB */
__device__ __half  g_ah[MROWS*DIM];        /* ln2 out fp16           24 MB */
__device__ __half  g_hh[MROWS*HID];        /* gelu hidden fp16       48 MB */
__device__ __half  g_w1h[8*HID*DIM];       /* fc1_w fp16             19 MB */
__device__ __half  g_w2h[8*DIM*HID];       /* fc2_w fp16             19 MB */
__device__ __half  g_wch[DIM*DIM];         /* conv_w fp16           1.2 MB */

/* ------------------------------ helpers ------------------------------ */
__global__ __launch_bounds__(256) void round_h(const float* __restrict__ s,
                                               __half* __restrict__ d, int n) {
    int i = blockIdx.x * 256 + threadIdx.x;
    if (i < n) d[i] = __float2half(s[i]);
}

/* vectorized im2col: one thread = one 16-px patch row (64B in, 32B out) */
__global__ __launch_bounds__(256) void im2col_k(const float* __restrict__ x,
                                                __half* __restrict__ out) {
    int gid = blockIdx.x * 256 + threadIdx.x;      /* 16384*48 */
    int r48 = gid % 48;
    int m   = gid / 48;
    int c   = r48 >> 4, ph = r48 & 15;
    int b = m >> 8;      int p  = m & 255;
    int hp = p >> 4;     int wp = p & 15;
    const float4* src = (const float4*)(x + ((size_t)(b*3 + c)*256 + hp*16 + ph)*256 + wp*16);
    __half2* dst = (__half2*)(out + (size_t)m * DIM + c*256 + ph*16);
    #pragma unroll
    for (int q = 0; q < 4; q++) {
        float4 v = src[q];
        dst[q*2+0] = __floats2half2_rn(v.x, v.y);
        dst[q*2+1] = __floats2half2_rn(v.z, v.w);
    }
}

__device__ __forceinline__ void ldsm4(uint32_t& r0, uint32_t& r1,
                                      uint32_t& r2, uint32_t& r3, uint32_t addr) {
    asm volatile("ldmatrix.sync.aligned.m8n8.x4.shared.b16 {%0,%1,%2,%3}, [%4];"
                 : "=r"(r0), "=r"(r1), "=r"(r2), "=r"(r3) : "r"(addr));
}
__device__ __forceinline__ void mma_f16(float* c, uint32_t a0, uint32_t a1,
                                        uint32_t a2, uint32_t a3,
                                        uint32_t b0, uint32_t b1) {
    asm volatile(
        "mma.sync.aligned.m16n8k16.row.col.f32.f16.f16.f32 "
        "{%0,%1,%2,%3},{%4,%5,%6,%7},{%8,%9},{%0,%1,%2,%3};"
        : "+f"(c[0]), "+f"(c[1]), "+f"(c[2]), "+f"(c[3])
        : "r"(a0), "r"(a1), "r"(a2), "r"(a3), "r"(b0), "r"(b1));
}

/* ------------------------------ fp16 tensor-core GEMM (R12 config) ------------------------------ */
/* CTA 128x64x32, 8 warps (4 M x 2 N), warp tile 32x32, 3-stage cp.async, static smem. */
#define RSTR 40
#define STGA (128*RSTR)
#define STGB (64*RSTR)
#define STG  (STGA+STGB)

template<int EPI>
__global__ __launch_bounds__(256) void gemm_mma(
    const __half* __restrict__ A, const __half* __restrict__ B,
    const float* __restrict__ bias, const float* __restrict__ extra,
    void* __restrict__ Cv, float2* __restrict__ stat, int M, int N, int K)
{
    __shared__ __half sm[3*STG];

    const int tid  = threadIdx.x;
    const int wid  = tid >> 5, lane = tid & 31;
    const int g    = lane >> 2, t = lane & 3;
    const int wm   = (wid & 3) * 32;
    const int wn   = (wid >> 2) * 32;
    const int m0   = blockIdx.y * 128, n0 = blockIdx.x * 64;

    float acc[2][4][4];
    #pragma unroll
    for (int i = 0; i < 2; i++)
        #pragma unroll
        for (int j = 0; j < 4; j++)
            #pragma unroll
            for (int q = 0; q < 4; q++) acc[i][j][q] = 0.f;

    const int nk = K >> 5;
    const int lrow = tid >> 2, lc = tid & 3;

    auto load_tiles = [&](int k0, int s) {
        __half* as = sm + s * STG;
        __half* bs = as + STGA;
        #pragma unroll
        for (int l = 0; l < 2; l++) {
            int row = lrow + l * 64;
            const __half* gA = A + (size_t)(m0 + row) * K + k0 + lc * 8;
            uint32_t sa = (uint32_t)__cvta_generic_to_shared(as + row * RSTR + lc * 8);
            asm volatile("cp.async.cg.shared.global [%0], [%1], 16;" :: "r"(sa), "l"(gA));
        }
        {
            const __half* gB = B + (size_t)(n0 + lrow) * K + k0 + lc * 8;
            uint32_t sb = (uint32_t)__cvta_generic_to_shared(bs + lrow * RSTR + lc * 8);
            asm volatile("cp.async.cg.shared.global [%0], [%1], 16;" :: "r"(sb), "l"(gB));
        }
        asm volatile("cp.async.commit_group;");
    };

    const int lq = lane >> 3, lr = lane & 7;
    const int a_row = (lq & 1) * 8 + lr;
    const int a_chk = lq >> 1;
    const int b_row = (lq >> 1) * 8 + lr;
    const int b_chk = lq & 1;

    load_tiles(0, 0);
    if (nk > 1) load_tiles(32, 1);

    int cur = 0, pre = 2;
    for (int it = 0; it < nk; it++) {
        if (it == nk - 1) { asm volatile("cp.async.wait_group 0;"); }
        else              { asm volatile("cp.async.wait_group 1;"); }
        __syncthreads();
        if (it + 2 < nk) load_tiles((it + 2) << 5, pre);

        const __half* as = sm + cur * STG;
        const __half* bs = as + STGA;
        #pragma unroll
        for (int ks = 0; ks < 2; ks++) {
            uint32_t aF[2][4];
            #pragma unroll
            for (int mi = 0; mi < 2; mi++) {
                uint32_t ad = (uint32_t)__cvta_generic_to_shared(
                    as + (wm + mi * 16 + a_row) * RSTR + (ks * 2 + a_chk) * 8);
                ldsm4(aF[mi][0], aF[mi][1], aF[mi][2], aF[mi][3], ad);
            }
            #pragma unroll
            for (int ni2 = 0; ni2 < 2; ni2++) {
                uint32_t b0, b1, b2, b3;
                uint32_t bd = (uint32_t)__cvta_generic_to_shared(
                    bs + (wn + ni2 * 16 + b_row) * RSTR + (ks * 2 + b_chk) * 8);
                ldsm4(b0, b1, b2, b3, bd);
                #pragma unroll
                for (int mi = 0; mi < 2; mi++) {
                    mma_f16(acc[mi][ni2*2],   aF[mi][0], aF[mi][1], aF[mi][2], aF[mi][3], b0, b1);
                    mma_f16(acc[mi][ni2*2+1], aF[mi][0], aF[mi][1], aF[mi][2], aF[mi][3], b2, b3);
                }
            }
        }
        cur = (cur == 2) ? 0 : cur + 1;
        pre = (pre == 2) ? 0 : pre + 1;
    }

    /* epilogue (+ per-row stats of produced residual for EPI 0/2) */
    float rs[2][2] = {{0.f,0.f},{0.f,0.f}};
    float rq[2][2] = {{0.f,0.f},{0.f,0.f}};

    #pragma unroll
    for (int mi = 0; mi < 2; mi++) {
        #pragma unroll
        for (int ni = 0; ni < 4; ni++) {
            int row = m0 + wm + mi * 16 + g;
            int col = n0 + wn + ni * 8 + 2 * t;
            float bc0 = bias[col], bc1 = bias[col + 1];
            #pragma unroll
            for (int hf = 0; hf < 2; hf++) {
                int m = row + hf * 8;
                float v0 = acc[mi][ni][hf*2]   + bc0;
                float v1 = acc[mi][ni][hf*2+1] + bc1;
                size_t o = (size_t)m * N + col;
                if (EPI == 0) {
                    const float* e = extra + (size_t)(m & 255) * N + col;
                    v0 += e[0]; v1 += e[1];
                    *(float2*)((float*)Cv + o) = make_float2(v0, v1);
                    rs[mi][hf] += v0 + v1;
                    rq[mi][hf] += v0*v0 + v1*v1;
                } else if (EPI == 1) {
                    v0 = 0.5f * v0 * (1.0f + erff(v0 * 0.70710678118654752f));
                    v1 = 0.5f * v1 * (1.0f + erff(v1 * 0.70710678118654752f));
                    *(__half2*)((__half*)Cv + o) = __floats2half2_rn(v0, v1);
                } else {
                    float2 old = *(float2*)((float*)Cv + o);
                    float n0f = old.x + v0, n1f = old.y + v1;
                    *(float2*)((float*)Cv + o) = make_float2(n0f, n1f);
                    rs[mi][hf] += n0f + n1f;
                    rq[mi][hf] += n0f*n0f + n1f*n1f;
                }
            }
        }
    }

    if (EPI != 1) {
        #pragma unroll
        for (int mi = 0; mi < 2; mi++) {
            #pragma unroll
            for (int hf = 0; hf < 2; hf++) {
                float s = rs[mi][hf], q = rq[mi][hf];
                s += __shfl_xor_sync(0xffffffffu, s, 1);
                q += __shfl_xor_sync(0xffffffffu, q, 1);
                s += __shfl_xor_sync(0xffffffffu, s, 2);
                q += __shfl_xor_sync(0xffffffffu, q, 2);
                if (t == 0) {
                    int m = m0 + wm + mi * 16 + g + hf * 8;
                    atomicAdd(&stat[m].x, s);
                    atomicAdd(&stat[m].y, q);
                }
            }
        }
    }
}

/* ------------------------------ reductions ------------------------------ */
__device__ __forceinline__ float2 block_reduce2(float s, float ss, float2* red) {
    int lane = threadIdx.x & 31, w = threadIdx.x >> 5;
    #pragma unroll
    for (int o = 16; o; o >>= 1) {
        s  += __shfl_down_sync(0xffffffffu, s,  o);
        ss += __shfl_down_sync(0xffffffffu, ss, o);
    }
    __syncthreads();
    if (lane == 0) red[w] = make_float2(s, ss);
    __syncthreads();
    if (w == 0) {
        float2 v = (lane < 8) ? red[lane] : make_float2(0.f, 0.f);
        float a = v.x, bq = v.y;
        #pragma unroll
        for (int o = 4; o; o >>= 1) {
            a  += __shfl_down_sync(0xffffffffu, a,  o);
            bq += __shfl_down_sync(0xffffffffu, bq, o);
        }
        if (lane == 0) red[0] = make_float2(a, bq);
    }
    __syncthreads();
    return red[0];
}

/* LayerNorm over fp16 input -> fp16 out (feeds fc1) */
__global__ __launch_bounds__(256) void ln_to_h(const __half* __restrict__ in,
                                               __half* __restrict__ out,
                                               const float* __restrict__ w,
                                               const float* __restrict__ b) {
    __shared__ float2 red[8];
    int row = blockIdx.x, t = threadIdx.x;
    const __half* r = in + (size_t)row * DIM;
    float v0 = __half2float(r[t]);
    float v1 = __half2float(r[t+256]);
    float v2 = __half2float(r[t+512]);
    float2 R = block_reduce2(v0+v1+v2, v0*v0+v1*v1+v2*v2, red);
    float mean = R.x * (1.f/768.f);
    float var  = R.y * (1.f/768.f) - mean*mean;
    float rs = rsqrtf(var + LN_EPS);
    __half* o = out + (size_t)row * DIM;
    o[t]     = __float2half((v0-mean)*rs*w[t]     + b[t]);
    o[t+256] = __float2half((v1-mean)*rs*w[t+256] + b[t+256]);
    o[t+512] = __float2half((v2-mean)*rs*w[t+512] + b[t+512]);
}

/* ------------------------------ 16-pt radix-4 complex FFT ------------------------------ */
/* In-place, natural order in and out.  sgn = -1 forward, +1 inverse. */
__device__ __forceinline__ void fft16_r4(float* xr, float* xi,
                                         const float* ct, const float* st,
                                         const float sgn) {
    float yr[4][4], yi[4][4];
    #pragma unroll
    for (int b = 0; b < 4; b++) {
        float a0r=xr[b],    a0i=xi[b];
        float a1r=xr[4+b],  a1i=xi[4+b];
        float a2r=xr[8+b],  a2i=xi[8+b];
        float a3r=xr[12+b], a3i=xi[12+b];
        float t0r=a0r+a2r, t0i=a0i+a2i;
        float t1r=a0r-a2r, t1i=a0i-a2i;
        float t2r=a1r+a3r, t2i=a1i+a3i;
        float t3r=a1r-a3r, t3i=a1i-a3i;
        float w3r = -sgn*t3i, w3i = sgn*t3r;
        float Br[4], Bi[4];
        Br[0]=t0r+t2r; Bi[0]=t0i+t2i;
        Br[1]=t1r+w3r; Bi[1]=t1i+w3i;
        Br[2]=t0r-t2r; Bi[2]=t0i-t2i;
        Br[3]=t1r-w3r; Bi[3]=t1i-w3i;
        #pragma unroll
        for (int c = 0; c < 4; c++) {
            int m = b * c;
            float wr = ct[m], wi = sgn*st[m];
            yr[c][b] = Br[c]*wr - Bi[c]*wi;
            yi[c][b] = Br[c]*wi + Bi[c]*wr;
        }
    }
    #pragma unroll
    for (int c = 0; c < 4; c++) {
        float t0r=yr[c][0]+yr[c][2], t0i=yi[c][0]+yi[c][2];
        float t1r=yr[c][0]-yr[c][2], t1i=yi[c][0]-yi[c][2];
        float t2r=yr[c][1]+yr[c][3], t2i=yi[c][1]+yi[c][3];
        float t3r=yr[c][1]-yr[c][3], t3i=yi[c][1]-yi[c][3];
        float w3r=-sgn*t3i, w3i=sgn*t3r;
        xr[c]    = t0r+t2r;  xi[c]    = t0i+t2i;
        xr[c+4]  = t1r+w3r;  xi[c+4]  = t1i+w3i;
        xr[c+8]  = t0r-t2r;  xi[c+8]  = t0i-t2i;
        xr[c+12] = t1r-w3r;  xi[c+12] = t1i-w3i;
    }
}

/* ------------------------------ fused global filter ------------------------------ */
/* One block = (batch b, 32-wide d-slice).  512 threads = (h 0..15, d 0..31).
   Phase 1: ln1 (fused stats) + radix-4 real FFT(w) -> fp32 smem spectrum.
   Phase 2: 288 threads: radix-4 FFT(h) * filter * iFFT(h) in registers.
   Phase 3: hermitian radix-4 inverse FFT(w) -> fp16 y.
   Smem banks: fr[h][k][d] h-stride = 288 floats = 0 mod 32 -> lane-private banks. */
__global__ __launch_bounds__(512) void fft_fused(
    const float* __restrict__ tt, const float2* __restrict__ stat,
    const float* __restrict__ lw, const float* __restrict__ lb,
    const float* __restrict__ cwl, __half* __restrict__ y)
{
    __shared__ float fr[16][9][32], fi[16][9][32];   /* 36 KB */
    __shared__ float ct[16], st[16], shm[256], shr[256];
    const int tid = threadIdx.x;
    const int b   = blockIdx.x;
    const int d0  = blockIdx.y * 32;
    if (tid < 16) { ct[tid] = cospif(tid * 0.125f); st[tid] = sinpif(tid * 0.125f); }
    if (tid < 256) {
        float2 sq = __ldg(&stat[b * 256 + tid]);
        float mean = sq.x * (1.f/768.f);
        float var  = sq.y * (1.f/768.f) - mean*mean;
        shm[tid] = mean;
        shr[tid] = rsqrtf(var + LN_EPS);
    }
    __syncthreads();

    const int d = tid & 31;
    const int h = tid >> 5;

    /* phase 1 */
    {
        float wd = lw[d0 + d], bd = lb[d0 + d];
        float v[16], vi[16];
        const float* src = tt + (size_t)(b * 256 + h * 16) * DIM + d0 + d;
        #pragma unroll
        for (int w = 0; w < 16; w++) {
            int r = h * 16 + w;
            v[w]  = (src[(size_t)w * DIM] - shm[r]) * shr[r] * wd + bd;
            vi[w] = 0.f;
        }
        fft16_r4(v, vi, ct, st, -1.f);
        #pragma unroll
        for (int k = 0; k < 9; k++) { fr[h][k][d] = v[k]; fi[h][k][d] = vi[k]; }
    }
    __syncthreads();

    /* phase 2 */
    if (tid < 288) {
        const int k = tid >> 5, d2 = tid & 31;
        float gr[16], gi[16];
        #pragma unroll
        for (int hh = 0; hh < 16; hh++) { gr[hh] = fr[hh][k][d2]; gi[hh] = fi[hh][k][d2]; }
        fft16_r4(gr, gi, ct, st, -1.f);
        #pragma unroll
        for (int u = 0; u < 16; u++) {
            const float* wp = cwl + ((size_t)(u * 9 + k) * DIM + d0 + d2) * 2;
            float wr = wp[0], wi = wp[1];
            float ar = gr[u], ai = gi[u];
            gr[u] = ar * wr - ai * wi;
            gi[u] = ar * wi + ai * wr;
        }
        fft16_r4(gr, gi, ct, st, 1.f);
        #pragma unroll
        for (int hh = 0; hh < 16; hh++) { fr[hh][k][d2] = gr[hh]; fi[hh][k][d2] = gi[hh]; }
    }
    __syncthreads();

    /* phase 3 */
    {
        float xr[16], xi[16];
        xr[0] = fr[h][0][d]; xi[0] = 0.f;
        #pragma unroll
        for (int k = 1; k < 8; k++) {
            xr[k] = fr[h][k][d];   xi[k] = fi[h][k][d];
            xr[16-k] = xr[k];      xi[16-k] = -xi[k];
        }
        xr[8] = fr[h][8][d]; xi[8] = 0.f;
        fft16_r4(xr, xi, ct, st, 1.f);
        __half* dst = y + (size_t)(b * 256 + h * 16) * DIM + d0 + d;
        #pragma unroll
        for (int w = 0; w < 16; w++)
            dst[(size_t)w * DIM] = __float2half(xr[w] * (1.f / 256.f));
    }
}

/* ------------------------------ final LN + mean + head (stats from g_stat) ------------------------------ */
__global__ __launch_bounds__(256) void head_k(const float* __restrict__ tt,
                                              const float2* __restrict__ stat,
                                              const float* __restrict__ nw,
                                              const float* __restrict__ nb,
                                              const float* __restrict__ hw,
                                              const float* __restrict__ hb,
                                              float* __restrict__ out) {
    __shared__ float2 red[8];
    int b = blockIdx.x, t = threadIdx.x;
    float a0 = 0.f, a1 = 0.f, a2 = 0.f;
    for (int p = 0; p < 256; p++) {
        int row = b*256 + p;
        float2 sq = __ldg(&stat[row]);
        float mean = sq.x * (1.f/768.f);
        float var  = sq.y * (1.f/768.f) - mean*mean;
        float rsd = rsqrtf(var + LN_EPS);
        const float* r = tt + (size_t)row * DIM;
        a0 += (r[t]     - mean) * rsd;
        a1 += (r[t+256] - mean) * rsd;
        a2 += (r[t+512] - mean) * rsd;
    }
    float f0 = a0 * nw[t]     * (1.f/256.f) + nb[t];
    float f1 = a1 * nw[t+256] * (1.f/256.f) + nb[t+256];
    float f2 = a2 * nw[t+512] * (1.f/256.f) + nb[t+512];
    float p0 = f0*hw[t]       + f1*hw[t+256]     + f2*hw[t+512];
    float p1 = f0*hw[768+t]   + f1*hw[768+t+256] + f2*hw[768+t+512];
    float2 R = block_reduce2(p0, p1, red);
    if (t == 0) {
        out[b*2 + 0] = R.x + hb[0];
        out[b*2 + 1] = R.y + hb[1];
    }
}

/* ------------------------------ launch ------------------------------ */
extern "C" void kernel_launch(void* const* d_in, const int* in_sizes, int n_in,
                              void* d_out, int out_size) {
    const float* x      = (const float*)d_in[0];
    const float* conv_w = (const float*)d_in[1];
    const float* conv_b = (const float*)d_in[2];
    const float* pos    = (const float*)d_in[3];
    const float* cw     = (const float*)d_in[4];
    const float* ln1w   = (const float*)d_in[5];
    const float* ln1b   = (const float*)d_in[6];
    const float* ln2w   = (const float*)d_in[7];
    const float* ln2b   = (const float*)d_in[8];
    const float* fc1w   = (const float*)d_in[9];
    const float* fc1b   = (const float*)d_in[10];
    const float* fc2w   = (const float*)d_in[11];
    const float* fc2b   = (const float*)d_in[12];
    const float* normw  = (const float*)d_in[13];
    const float* normb  = (const float*)d_in[14];
    const float* headw  = (const float*)d_in[15];
    const float* headb  = (const float*)d_in[16];
    float* out = (float*)d_out;
    (void)in_sizes; (void)n_in; (void)out_size;

    float *pt;
    float2* pstat;
    __half *pyh, *pxh, *pah, *phh, *pw1h, *pw2h, *pwch;
    cudaGetSymbolAddress((void**)&pt,    g_t);
    cudaGetSymbolAddress((void**)&pyh,   g_yh);
    cudaGetSymbolAddress((void**)&pstat, g_stat);
    cudaGetSymbolAddress((void**)&pxh,   g_xh);
    cudaGetSymbolAddress((void**)&pah,   g_ah);
    cudaGetSymbolAddress((void**)&phh,   g_hh);
    cudaGetSymbolAddress((void**)&pw1h,  g_w1h);
    cudaGetSymbolAddress((void**)&pw2h,  g_w2h);
    cudaGetSymbolAddress((void**)&pwch,  g_wch);

    /* fp16 weights */
    round_h<<<(DIM*DIM + 255)/256, 256>>>(conv_w, pwch, DIM*DIM);
    round_h<<<(8*HID*DIM + 255)/256, 256>>>(fc1w, pw1h, 8*HID*DIM);
    round_h<<<(8*DIM*HID + 255)/256, 256>>>(fc2w, pw2h, 8*DIM*HID);

    /* patch embed (+ ln1 stats for layer 0) */
    im2col_k<<<(MROWS * 48) / 256, 256>>>(x, pxh);
    cudaMemsetAsync(pstat, 0, MROWS * sizeof(float2));
    gemm_mma<0><<<dim3(DIM/64, MROWS/128), 256>>>(pxh, pwch, conv_b, pos, pt, pstat,
                                                  MROWS, DIM, DIM);

    for (int i = 0; i < 8; i++) {
        fft_fused<<<dim3(BATCH, DIM/32), 512>>>(pt, pstat, ln1w + i*DIM, ln1b + i*DIM,
                                                cw + (size_t)i * 16 * 9 * DIM * 2, pyh);
        ln_to_h<<<MROWS, 256>>>(pyh, pah, ln2w + i*DIM, ln2b + i*DIM);
        gemm_mma<1><<<dim3(HID/64, MROWS/128), 256>>>(
            pah, pw1h + (size_t)i*HID*DIM, fc1b + i*HID, nullptr, phh, nullptr,
            MROWS, HID, DIM);
        cudaMemsetAsync(pstat, 0, MROWS * sizeof(float2));
        gemm_mma<2><<<dim3(DIM/64, MROWS/128), 256>>>(
            phh, pw2h + (size_t)i*DIM*HID, fc2b + i*DIM, nullptr, pt, pstat,
            MROWS, DIM, HID);
    }

    head_k<<<BATCH, 256>>>(pt, pstat, normw, normb, headw, headb, out);
}

// round 15
// speedup vs baseline: 1.0942x; 1.0279x over previous
#include <cuda_runtime.h>
#include <cuda_fp16.h>
#include <math.h>
#include <stdint.h>

#define DIM 768
#define HID 1536
#define BATCH 64
#define TOK 256
#define MROWS (BATCH*TOK)   /* 16384 */
#define LN_EPS 1e-6f

/* ------------------------------ scratch ------------------------------ */
__device__ float   g_t [MROWS*DIM];        /* residual stream fp32   48 MB */
__device__ __half  g_yh[MROWS*DIM];        /* FFT out fp16           24 MB */
__device__ float2  g_stat[MROWS];          /* ln1 (sum, sumsq) per row     */
__device__ __half  g_xh[MROWS*DIM];        /* im2col fp16            24 MB */
__device__ __half  g_ah[MROWS*DIM];        /* ln2 out fp16           24 MB */
__device__ __half  g_hh[MROWS*HID];        /* gelu hidden fp16       48 MB */
__device__ __half  g_w1h[8*HID*DIM];       /* fc1_w fp16             19 MB */
__device__ __half  g_w2h[8*DIM*HID];       /* fc2_w fp16             19 MB */
__device__ __half  g_wch[DIM*DIM];         /* conv_w fp16           1.2 MB */

/* ------------------------------ helpers ------------------------------ */
__global__ __launch_bounds__(256) void round_h(const float* __restrict__ s,
                                               __half* __restrict__ d, int n) {
    int i = blockIdx.x * 256 + threadIdx.x;
    if (i < n) d[i] = __float2half(s[i]);
}

/* vectorized im2col: one thread = one 16-px patch row (64B in, 32B out) */
__global__ __launch_bounds__(256) void im2col_k(const float* __restrict__ x,
                                                __half* __restrict__ out) {
    int gid = blockIdx.x * 256 + threadIdx.x;      /* 16384*48 */
    int r48 = gid % 48;
    int m   = gid / 48;
    int c   = r48 >> 4, ph = r48 & 15;
    int b = m >> 8;      int p  = m & 255;
    int hp = p >> 4;     int wp = p & 15;
    const float4* src = (const float4*)(x + ((size_t)(b*3 + c)*256 + hp*16 + ph)*256 + wp*16);
    __half2* dst = (__half2*)(out + (size_t)m * DIM + c*256 + ph*16);
    #pragma unroll
    for (int q = 0; q < 4; q++) {
        float4 v = src[q];
        dst[q*2+0] = __floats2half2_rn(v.x, v.y);
        dst[q*2+1] = __floats2half2_rn(v.z, v.w);
    }
}

__device__ __forceinline__ void ldsm4(uint32_t& r0, uint32_t& r1,
                                      uint32_t& r2, uint32_t& r3, uint32_t addr) {
    asm volatile("ldmatrix.sync.aligned.m8n8.x4.shared.b16 {%0,%1,%2,%3}, [%4];"
                 : "=r"(r0), "=r"(r1), "=r"(r2), "=r"(r3) : "r"(addr));
}
__device__ __forceinline__ void mma_f16(float* c, uint32_t a0, uint32_t a1,
                                        uint32_t a2, uint32_t a3,
                                        uint32_t b0, uint32_t b1) {
    asm volatile(
        "mma.sync.aligned.m16n8k16.row.col.f32.f16.f16.f32 "
        "{%0,%1,%2,%3},{%4,%5,%6,%7},{%8,%9},{%0,%1,%2,%3};"
        : "+f"(c[0]), "+f"(c[1]), "+f"(c[2]), "+f"(c[3])
        : "r"(a0), "r"(a1), "r"(a2), "r"(a3), "r"(b0), "r"(b1));
}

/* ------------------------------ fp16 tensor-core GEMM (R12 config) ------------------------------ */
#define RSTR 40
#define STGA (128*RSTR)
#define STGB (64*RSTR)
#define STG  (STGA+STGB)

template<int EPI>
__global__ __launch_bounds__(256) void gemm_mma(
    const __half* __restrict__ A, const __half* __restrict__ B,
    const float* __restrict__ bias, const float* __restrict__ extra,
    void* __restrict__ Cv, float2* __restrict__ stat, int M, int N, int K)
{
    __shared__ __half sm[3*STG];

    const int tid  = threadIdx.x;
    const int wid  = tid >> 5, lane = tid & 31;
    const int g    = lane >> 2, t = lane & 3;
    const int wm   = (wid & 3) * 32;
    const int wn   = (wid >> 2) * 32;
    const int m0   = blockIdx.y * 128, n0 = blockIdx.x * 64;

    float acc[2][4][4];
    #pragma unroll
    for (int i = 0; i < 2; i++)
        #pragma unroll
        for (int j = 0; j < 4; j++)
            #pragma unroll
            for (int q = 0; q < 4; q++) acc[i][j][q] = 0.f;

    const int nk = K >> 5;
    const int lrow = tid >> 2, lc = tid & 3;

    auto load_tiles = [&](int k0, int s) {
        __half* as = sm + s * STG;
        __half* bs = as + STGA;
        #pragma unroll
        for (int l = 0; l < 2; l++) {
            int row = lrow + l * 64;
            const __half* gA = A + (size_t)(m0 + row) * K + k0 + lc * 8;
            uint32_t sa = (uint32_t)__cvta_generic_to_shared(as + row * RSTR + lc * 8);
            asm volatile("cp.async.cg.shared.global [%0], [%1], 16;" :: "r"(sa), "l"(gA));
        }
        {
            const __half* gB = B + (size_t)(n0 + lrow) * K + k0 + lc * 8;
            uint32_t sb = (uint32_t)__cvta_generic_to_shared(bs + lrow * RSTR + lc * 8);
            asm volatile("cp.async.cg.shared.global [%0], [%1], 16;" :: "r"(sb), "l"(gB));
        }
        asm volatile("cp.async.commit_group;");
    };

    const int lq = lane >> 3, lr = lane & 7;
    const int a_row = (lq & 1) * 8 + lr;
    const int a_chk = lq >> 1;
    const int b_row = (lq >> 1) * 8 + lr;
    const int b_chk = lq & 1;

    load_tiles(0, 0);
    if (nk > 1) load_tiles(32, 1);

    int cur = 0, pre = 2;
    for (int it = 0; it < nk; it++) {
        if (it == nk - 1) { asm volatile("cp.async.wait_group 0;"); }
        else              { asm volatile("cp.async.wait_group 1;"); }
        __syncthreads();
        if (it + 2 < nk) load_tiles((it + 2) << 5, pre);

        const __half* as = sm + cur * STG;
        const __half* bs = as + STGA;
        #pragma unroll
        for (int ks = 0; ks < 2; ks++) {
            uint32_t aF[2][4];
            #pragma unroll
            for (int mi = 0; mi < 2; mi++) {
                uint32_t ad = (uint32_t)__cvta_generic_to_shared(
                    as + (wm + mi * 16 + a_row) * RSTR + (ks * 2 + a_chk) * 8);
                ldsm4(aF[mi][0], aF[mi][1], aF[mi][2], aF[mi][3], ad);
            }
            #pragma unroll
            for (int ni2 = 0; ni2 < 2; ni2++) {
                uint32_t b0, b1, b2, b3;
                uint32_t bd = (uint32_t)__cvta_generic_to_shared(
                    bs + (wn + ni2 * 16 + b_row) * RSTR + (ks * 2 + b_chk) * 8);
                ldsm4(b0, b1, b2, b3, bd);
                #pragma unroll
                for (int mi = 0; mi < 2; mi++) {
                    mma_f16(acc[mi][ni2*2],   aF[mi][0], aF[mi][1], aF[mi][2], aF[mi][3], b0, b1);
                    mma_f16(acc[mi][ni2*2+1], aF[mi][0], aF[mi][1], aF[mi][2], aF[mi][3], b2, b3);
                }
            }
        }
        cur = (cur == 2) ? 0 : cur + 1;
        pre = (pre == 2) ? 0 : pre + 1;
    }

    /* epilogue (+ per-row stats of produced residual for EPI 0/2) */
    float rs[2][2] = {{0.f,0.f},{0.f,0.f}};
    float rq[2][2] = {{0.f,0.f},{0.f,0.f}};

    #pragma unroll
    for (int mi = 0; mi < 2; mi++) {
        #pragma unroll
        for (int ni = 0; ni < 4; ni++) {
            int row = m0 + wm + mi * 16 + g;
            int col = n0 + wn + ni * 8 + 2 * t;
            float bc0 = bias[col], bc1 = bias[col + 1];
            #pragma unroll
            for (int hf = 0; hf < 2; hf++) {
                int m = row + hf * 8;
                float v0 = acc[mi][ni][hf*2]   + bc0;
                float v1 = acc[mi][ni][hf*2+1] + bc1;
                size_t o = (size_t)m * N + col;
                if (EPI == 0) {
                    const float* e = extra + (size_t)(m & 255) * N + col;
                    v0 += e[0]; v1 += e[1];
                    *(float2*)((float*)Cv + o) = make_float2(v0, v1);
                    rs[mi][hf] += v0 + v1;
                    rq[mi][hf] += v0*v0 + v1*v1;
                } else if (EPI == 1) {
                    v0 = 0.5f * v0 * (1.0f + erff(v0 * 0.70710678118654752f));
                    v1 = 0.5f * v1 * (1.0f + erff(v1 * 0.70710678118654752f));
                    *(__half2*)((__half*)Cv + o) = __floats2half2_rn(v0, v1);
                } else {
                    float2 old = *(float2*)((float*)Cv + o);
                    float n0f = old.x + v0, n1f = old.y + v1;
                    *(float2*)((float*)Cv + o) = make_float2(n0f, n1f);
                    rs[mi][hf] += n0f + n1f;
                    rq[mi][hf] += n0f*n0f + n1f*n1f;
                }
            }
        }
    }

    if (EPI != 1) {
        #pragma unroll
        for (int mi = 0; mi < 2; mi++) {
            #pragma unroll
            for (int hf = 0; hf < 2; hf++) {
                float s = rs[mi][hf], q = rq[mi][hf];
                s += __shfl_xor_sync(0xffffffffu, s, 1);
                q += __shfl_xor_sync(0xffffffffu, q, 1);
                s += __shfl_xor_sync(0xffffffffu, s, 2);
                q += __shfl_xor_sync(0xffffffffu, q, 2);
                if (t == 0) {
                    int m = m0 + wm + mi * 16 + g + hf * 8;
                    atomicAdd(&stat[m].x, s);
                    atomicAdd(&stat[m].y, q);
                }
            }
        }
    }
}

/* ------------------------------ reductions ------------------------------ */
__device__ __forceinline__ float2 block_reduce2(float s, float ss, float2* red) {
    int lane = threadIdx.x & 31, w = threadIdx.x >> 5;
    #pragma unroll
    for (int o = 16; o; o >>= 1) {
        s  += __shfl_down_sync(0xffffffffu, s,  o);
        ss += __shfl_down_sync(0xffffffffu, ss, o);
    }
    __syncthreads();
    if (lane == 0) red[w] = make_float2(s, ss);
    __syncthreads();
    if (w == 0) {
        float2 v = (lane < 8) ? red[lane] : make_float2(0.f, 0.f);
        float a = v.x, bq = v.y;
        #pragma unroll
        for (int o = 4; o; o >>= 1) {
            a  += __shfl_down_sync(0xffffffffu, a,  o);
            bq += __shfl_down_sync(0xffffffffu, bq, o);
        }
        if (lane == 0) red[0] = make_float2(a, bq);
    }
    __syncthreads();
    return red[0];
}

/* warp-per-row LayerNorm fp16 -> fp16 (feeds fc1): shfl-only, no block barriers */
__global__ __launch_bounds__(256) void ln_to_h(const __half* __restrict__ in,
                                               __half* __restrict__ out,
                                               const float* __restrict__ w,
                                               const float* __restrict__ b) {
    const int lane = threadIdx.x & 31, warp = threadIdx.x >> 5;
    const int row  = blockIdx.x * 8 + warp;
    const __half2* r = (const __half2*)(in + (size_t)row * DIM);

    float2 v[12];
    float s = 0.f, q = 0.f;
    #pragma unroll
    for (int j = 0; j < 12; j++) {
        v[j] = __half22float2(r[lane + 32*j]);
        s += v[j].x + v[j].y;
        q += v[j].x*v[j].x + v[j].y*v[j].y;
    }
    #pragma unroll
    for (int o = 16; o; o >>= 1) {
        s += __shfl_xor_sync(0xffffffffu, s, o);
        q += __shfl_xor_sync(0xffffffffu, q, o);
    }
    float mean = s * (1.f/768.f);
    float var  = q * (1.f/768.f) - mean*mean;
    float rsd  = rsqrtf(var + LN_EPS);

    __half2* o2 = (__half2*)(out + (size_t)row * DIM);
    const float2* w2 = (const float2*)w;
    const float2* b2 = (const float2*)b;
    #pragma unroll
    for (int j = 0; j < 12; j++) {
        int idx = lane + 32*j;
        float2 ww = w2[idx], bb = b2[idx];
        float o0 = (v[j].x - mean) * rsd * ww.x + bb.x;
        float o1 = (v[j].y - mean) * rsd * ww.y + bb.y;
        o2[idx] = __floats2half2_rn(o0, o1);
    }
}

/* ------------------------------ 16-pt radix-4 complex FFT ------------------------------ */
__device__ __forceinline__ void fft16_r4(float* xr, float* xi,
                                         const float* ct, const float* st,
                                         const float sgn) {
    float yr[4][4], yi[4][4];
    #pragma unroll
    for (int b = 0; b < 4; b++) {
        float a0r=xr[b],    a0i=xi[b];
        float a1r=xr[4+b],  a1i=xi[4+b];
        float a2r=xr[8+b],  a2i=xi[8+b];
        float a3r=xr[12+b], a3i=xi[12+b];
        float t0r=a0r+a2r, t0i=a0i+a2i;
        float t1r=a0r-a2r, t1i=a0i-a2i;
        float t2r=a1r+a3r, t2i=a1i+a3i;
        float t3r=a1r-a3r, t3i=a1i-a3i;
        float w3r = -sgn*t3i, w3i = sgn*t3r;
        float Br[4], Bi[4];
        Br[0]=t0r+t2r; Bi[0]=t0i+t2i;
        Br[1]=t1r+w3r; Bi[1]=t1i+w3i;
        Br[2]=t0r-t2r; Bi[2]=t0i-t2i;
        Br[3]=t1r-w3r; Bi[3]=t1i-w3i;
        #pragma unroll
        for (int c = 0; c < 4; c++) {
            int m = b * c;
            float wr = ct[m], wi = sgn*st[m];
            yr[c][b] = Br[c]*wr - Bi[c]*wi;
            yi[c][b] = Br[c]*wi + Bi[c]*wr;
        }
    }
    #pragma unroll
    for (int c = 0; c < 4; c++) {
        float t0r=yr[c][0]+yr[c][2], t0i=yi[c][0]+yi[c][2];
        float t1r=yr[c][0]-yr[c][2], t1i=yi[c][0]-yi[c][2];
        float t2r=yr[c][1]+yr[c][3], t2i=yi[c][1]+yi[c][3];
        float t3r=yr[c][1]-yr[c][3], t3i=yi[c][1]-yi[c][3];
        float w3r=-sgn*t3i, w3i=sgn*t3r;
        xr[c]    = t0r+t2r;  xi[c]    = t0i+t2i;
        xr[c+4]  = t1r+w3r;  xi[c+4]  = t1i+w3i;
        xr[c+8]  = t0r-t2r;  xi[c+8]  = t0i-t2i;
        xr[c+12] = t1r-w3r;  xi[c+12] = t1i-w3i;
    }
}

/* ------------------------------ fused global filter ------------------------------ */
__global__ __launch_bounds__(512) void fft_fused(
    const float* __restrict__ tt, const float2* __restrict__ stat,
    const float* __restrict__ lw, const float* __restrict__ lb,
    const float* __restrict__ cwl, __half* __restrict__ y)
{
    __shared__ float fr[16][9][32], fi[16][9][32];   /* 36 KB */
    __shared__ float ct[16], st[16], shm[256], shr[256];
    const int tid = threadIdx.x;
    const int b   = blockIdx.x;
    const int d0  = blockIdx.y * 32;
    if (tid < 16) { ct[tid] = cospif(tid * 0.125f); st[tid] = sinpif(tid * 0.125f); }
    if (tid < 256) {
        float2 sq = __ldg(&stat[b * 256 + tid]);
        float mean = sq.x * (1.f/768.f);
        float var  = sq.y * (1.f/768.f) - mean*mean;
        shm[tid] = mean;
        shr[tid] = rsqrtf(var + LN_EPS);
    }
    __syncthreads();

    const int d = tid & 31;
    const int h = tid >> 5;

    /* phase 1: ln1 + real FFT(w) */
    {
        float wd = lw[d0 + d], bd = lb[d0 + d];
        float v[16], vi[16];
        const float* src = tt + (size_t)(b * 256 + h * 16) * DIM + d0 + d;
        #pragma unroll
        for (int w = 0; w < 16; w++) {
            int r = h * 16 + w;
            v[w]  = (src[(size_t)w * DIM] - shm[r]) * shr[r] * wd + bd;
            vi[w] = 0.f;
        }
        fft16_r4(v, vi, ct, st, -1.f);
        #pragma unroll
        for (int k = 0; k < 9; k++) { fr[h][k][d] = v[k]; fi[h][k][d] = vi[k]; }
    }
    __syncthreads();

    /* phase 2: FFT(h) * filter * iFFT(h) */
    if (tid < 288) {
        const int k = tid >> 5, d2 = tid & 31;
        float gr[16], gi[16];
        #pragma unroll
        for (int hh = 0; hh < 16; hh++) { gr[hh] = fr[hh][k][d2]; gi[hh] = fi[hh][k][d2]; }
        fft16_r4(gr, gi, ct, st, -1.f);
        #pragma unroll
        for (int u = 0; u < 16; u++) {
            const float* wp = cwl + ((size_t)(u * 9 + k) * DIM + d0 + d2) * 2;
            float wr = wp[0], wi = wp[1];
            float ar = gr[u], ai = gi[u];
            gr[u] = ar * wr - ai * wi;
            gi[u] = ar * wi + ai * wr;
        }
        fft16_r4(gr, gi, ct, st, 1.f);
        #pragma unroll
        for (int hh = 0; hh < 16; hh++) { fr[hh][k][d2] = gr[hh]; fi[hh][k][d2] = gi[hh]; }
    }
    __syncthreads();

    /* phase 3: hermitian inverse FFT(w) -> fp16 y */
    {
        float xr[16], xi[16];
        xr[0] = fr[h][0][d]; xi[0] = 0.f;
        #pragma unroll
        for (int k = 1; k < 8; k++) {
            xr[k] = fr[h][k][d];   xi[k] = fi[h][k][d];
            xr[16-k] = xr[k];      xi[16-k] = -xi[k];
        }
        xr[8] = fr[h][8][d]; xi[8] = 0.f;
        fft16_r4(xr, xi, ct, st, 1.f);
        __half* dst = y + (size_t)(b * 256 + h * 16) * DIM + d0 + d;
        #pragma unroll
        for (int w = 0; w < 16; w++)
            dst[(size_t)w * DIM] = __float2half(xr[w] * (1.f / 256.f));
    }
}

/* ------------------------------ final LN + mean + head (stats from g_stat) ------------------------------ */
__global__ __launch_bounds__(256) void head_k(const float* __restrict__ tt,
                                              const float2* __restrict__ stat,
                                              const float* __restrict__ nw,
                                              const float* __restrict__ nb,
                                              const float* __restrict__ hw,
                                              const float* __restrict__ hb,
                                              float* __restrict__ out) {
    __shared__ float2 red[8];
    int b = blockIdx.x, t = threadIdx.x;
    float a0 = 0.f, a1 = 0.f, a2 = 0.f;
    for (int p = 0; p < 256; p++) {
        int row = b*256 + p;
        float2 sq = __ldg(&stat[row]);
        float mean = sq.x * (1.f/768.f);
        float var  = sq.y * (1.f/768.f) - mean*mean;
        float rsd = rsqrtf(var + LN_EPS);
        const float* r = tt + (size_t)row * DIM;
        a0 += (r[t]     - mean) * rsd;
        a1 += (r[t+256] - mean) * rsd;
        a2 += (r[t+512] - mean) * rsd;
    }
    float f0 = a0 * nw[t]     * (1.f/256.f) + nb[t];
    float f1 = a1 * nw[t+256] * (1.f/256.f) + nb[t+256];
    float f2 = a2 * nw[t+512] * (1.f/256.f) + nb[t+512];
    float p0 = f0*hw[t]       + f1*hw[t+256]     + f2*hw[t+512];
    float p1 = f0*hw[768+t]   + f1*hw[768+t+256] + f2*hw[768+t+512];
    float2 R = block_reduce2(p0, p1, red);
    if (t == 0) {
        out[b*2 + 0] = R.x + hb[0];
        out[b*2 + 1] = R.y + hb[1];
    }
}

/* ------------------------------ launch ------------------------------ */
extern "C" void kernel_launch(void* const* d_in, const int* in_sizes, int n_in,
                              void* d_out, int out_size) {
    const float* x      = (const float*)d_in[0];
    const float* conv_w = (const float*)d_in[1];
    const float* conv_b = (const float*)d_in[2];
    const float* pos    = (const float*)d_in[3];
    const float* cw     = (const float*)d_in[4];
    const float* ln1w   = (const float*)d_in[5];
    const float* ln1b   = (const float*)d_in[6];
    const float* ln2w   = (const float*)d_in[7];
    const float* ln2b   = (const float*)d_in[8];
    const float* fc1w   = (const float*)d_in[9];
    const float* fc1b   = (const float*)d_in[10];
    const float* fc2w   = (const float*)d_in[11];
    const float* fc2b   = (const float*)d_in[12];
    const float* normw  = (const float*)d_in[13];
    const float* normb  = (const float*)d_in[14];
    const float* headw  = (const float*)d_in[15];
    const float* headb  = (const float*)d_in[16];
    float* out = (float*)d_out;
    (void)in_sizes; (void)n_in; (void)out_size;

    float *pt;
    float2* pstat;
    __half *pyh, *pxh, *pah, *phh, *pw1h, *pw2h, *pwch;
    cudaGetSymbolAddress((void**)&pt,    g_t);
    cudaGetSymbolAddress((void**)&pyh,   g_yh);
    cudaGetSymbolAddress((void**)&pstat, g_stat);
    cudaGetSymbolAddress((void**)&pxh,   g_xh);
    cudaGetSymbolAddress((void**)&pah,   g_ah);
    cudaGetSymbolAddress((void**)&phh,   g_hh);
    cudaGetSymbolAddress((void**)&pw1h,  g_w1h);
    cudaGetSymbolAddress((void**)&pw2h,  g_w2h);
    cudaGetSymbolAddress((void**)&pwch,  g_wch);

    /* fp16 weights */
    round_h<<<(DIM*DIM + 255)/256, 256>>>(conv_w, pwch, DIM*DIM);
    round_h<<<(8*HID*DIM + 255)/256, 256>>>(fc1w, pw1h, 8*HID*DIM);
    round_h<<<(8*DIM*HID + 255)/256, 256>>>(fc2w, pw2h, 8*DIM*HID);

    /* patch embed (+ ln1 stats for layer 0) */
    im2col_k<<<(MROWS * 48) / 256, 256>>>(x, pxh);
    cudaMemsetAsync(pstat, 0, MROWS * sizeof(float2));
    gemm_mma<0><<<dim3(DIM/64, MROWS/128), 256>>>(pxh, pwch, conv_b, pos, pt, pstat,
                                                  MROWS, DIM, DIM);

    for (int i = 0; i < 8; i++) {
        fft_fused<<<dim3(BATCH, DIM/32), 512>>>(pt, pstat, ln1w + i*DIM, ln1b + i*DIM,
                                                cw + (size_t)i * 16 * 9 * DIM * 2, pyh);
        ln_to_h<<<MROWS/8, 256>>>(pyh, pah, ln2w + i*DIM, ln2b + i*DIM);
        gemm_mma<1><<<dim3(HID/64, MROWS/128), 256>>>(
            pah, pw1h + (size_t)i*HID*DIM, fc1b + i*HID, nullptr, phh, nullptr,
            MROWS, HID, DIM);
        cudaMemsetAsync(pstat, 0, MROWS * sizeof(float2));
        gemm_mma<2><<<dim3(DIM/64, MROWS/128), 256>>>(
            phh, pw2h + (size_t)i*DIM*HID, fc2b + i*DIM, nullptr, pt, pstat,
            MROWS, DIM, HID);
    }

    head_k<<<BATCH, 256>>>(pt, pstat, normw, normb, headw, headb, out);
}